// round 6
// baseline (speedup 1.0000x reference)
#include <cuda_runtime.h>
#include <cstdint>

#define T_TOKENS 16384
#define DIMX     2048
#define NE       8
#define KSEL     2048

// libdevice exp — exact bits, immune to fast-math flags.
extern "C" __device__ float __nv_expf(float);

// Scratch: per-expert sort keys (key = ~bits(sigmoid(logit))) and a global
// 16-bit histogram of keys per expert (level 0 of the radix select).
__device__ unsigned int g_keys[NE * T_TOKENS];
__device__ unsigned int g_hist[NE * 65536];

// ---------------------------------------------------------------------------
// Kernel 1: logits + keys + global key-histogram.
// Thread (t,e): full 2048-dim in-order scalar fma.rn chain (bitwise identical
// to R4/R5). Manual software pipeline: group g+1's x/w loads issue before
// group g's FMA chain, so the 29-cyc LDS latency hides under the 16-cyc
// FFMA chain instead of serializing with it.
// ---------------------------------------------------------------------------
#define TILE_T     64
#define K1_THREADS 512
#define CHUNK      64
#define XP         68   // x tile pitch: conflict-free broadcast LDS.128
#define WPC        68   // w chunk pitch: experts land on distinct bank quads

__global__ void __launch_bounds__(K1_THREADS, 2) k1_gemv(const float* __restrict__ x,
                                                         const float* __restrict__ W)
{
    __shared__ float sx[TILE_T * XP];   // 17.4 KB
    __shared__ float sw[NE * WPC];      //  2.2 KB

    const int tid  = threadIdx.x;
    const int tloc = tid >> 3;          // token within tile
    const int e    = tid & 7;           // expert
    const size_t rowBase = (size_t)blockIdx.x * TILE_T;

    const int r0 = tid >> 4;            // staging row (0..31); second is r0+32
    const int c0 = tid & 15;            // staging float4 col

    float4 px0, px1, pw;
    {
        const float* xb = x + rowBase * DIMX;
        px0 = *reinterpret_cast<const float4*>(xb + (size_t)r0 * DIMX + c0 * 4);
        px1 = *reinterpret_cast<const float4*>(xb + (size_t)(r0 + 32) * DIMX + c0 * 4);
        if (tid < 128)
            pw = *reinterpret_cast<const float4*>(W + (tid >> 4) * DIMX + (tid & 15) * 4);
    }

    float acc = 0.0f;

    for (int ch = 0; ch < DIMX / CHUNK; ++ch) {
        __syncthreads();   // previous chunk's reads complete
        *reinterpret_cast<float4*>(&sx[r0 * XP + c0 * 4]) = px0;
        *reinterpret_cast<float4*>(&sx[(r0 + 32) * XP + c0 * 4]) = px1;
        if (tid < 128)
            *reinterpret_cast<float4*>(&sw[(tid >> 4) * WPC + (tid & 15) * 4]) = pw;
        __syncthreads();   // tiles visible

        if (ch + 1 < DIMX / CHUNK) {   // prefetch next chunk (lands during compute)
            const float* xb = x + rowBase * DIMX + (ch + 1) * CHUNK;
            px0 = *reinterpret_cast<const float4*>(xb + (size_t)r0 * DIMX + c0 * 4);
            px1 = *reinterpret_cast<const float4*>(xb + (size_t)(r0 + 32) * DIMX + c0 * 4);
            if (tid < 128)
                pw = *reinterpret_cast<const float4*>(
                         W + (tid >> 4) * DIMX + (ch + 1) * CHUNK + (tid & 15) * 4);
        }

        const float* xd = sx + tloc * XP;
        const float* wd = sw + e * WPC;
        float4 xv = *reinterpret_cast<const float4*>(xd);
        float4 wv = *reinterpret_cast<const float4*>(wd);
#pragma unroll
        for (int g = 0; g < CHUNK / 4; ++g) {
            float4 xn, wn;
            if (g < CHUNK / 4 - 1) {
                xn = *reinterpret_cast<const float4*>(xd + (g + 1) * 4);
                wn = *reinterpret_cast<const float4*>(wd + (g + 1) * 4);
            }
            acc = __fmaf_rn(xv.x, wv.x, acc);
            acc = __fmaf_rn(xv.y, wv.y, acc);
            acc = __fmaf_rn(xv.z, wv.z, acc);
            acc = __fmaf_rn(xv.w, wv.w, acc);
            if (g < CHUNK / 4 - 1) { xv = xn; wv = wn; }
        }
    }

    // sigmoid (exp form, bit-matched) -> monotone descending key
    float em = __nv_expf(-acc);
    float s  = __fdiv_rn(1.0f, __fadd_rn(1.0f, em));
    unsigned key = ~__float_as_uint(s);
    g_keys[e * T_TOKENS + (int)rowBase + tloc] = key;

    // global 16-bit histogram (level 0 of the select), warp-aggregated
    unsigned hidx = (unsigned)e * 65536u + (key >> 16);
    unsigned same = __match_any_sync(0xffffffffu, hidx);
    if ((int)(tid & 31) == __ffs(same) - 1)
        atomicAdd(&g_hist[hidx], (unsigned)__popc(same));
}

// ---------------------------------------------------------------------------
// Kernel 2: per-expert exact top-2048 (desc, ties -> lower index).
// 46-bit key K = (key32 << 14) | token. Level 0 = precomputed global 16-bit
// histogram; 3 in-block levels (12/12/6 bits) over register-resident keys;
// collect; hybrid bitonic sort (smem j>=64, shfl j<=32).
// ---------------------------------------------------------------------------
#define K2_THREADS 1024
#define HC         4
#define MASK46     ((1ull << 46) - 1)

__global__ void __launch_bounds__(K2_THREADS) k2_topk(float* __restrict__ out, int writeIdx)
{
    extern __shared__ unsigned char sm2[];
    unsigned int*        hist  = reinterpret_cast<unsigned int*>(sm2);            // HC x 4096 (64KB)
    unsigned int*        hscan = reinterpret_cast<unsigned int*>(sm2 + 65536);    // 4096 (16KB)
    unsigned long long*  sel   = reinterpret_cast<unsigned long long*>(sm2 + 81920); // 2048 u64 (16KB)

    __shared__ unsigned int s_wsum[32];
    __shared__ unsigned long long s_pref;
    __shared__ unsigned long long s_mask;
    __shared__ int          s_want;
    __shared__ int          s_bin;
    __shared__ unsigned int s_before;
    __shared__ int          s_exact;
    __shared__ int          s_n;

    const int e    = blockIdx.x;
    const int tid  = threadIdx.x;
    const unsigned lane = tid & 31;
    const int wid  = tid >> 5;

    // Keys in registers: kreg[r] = key of token (tid + r*1024).
    unsigned kreg[16];
    {
        const unsigned* gk = g_keys + e * T_TOKENS;
#pragma unroll
        for (int r = 0; r < 16; ++r)
            kreg[r] = gk[tid + r * K2_THREADS];
    }

    if (tid == 0) { s_exact = 0; s_n = 0; }
    __syncthreads();

    // ---- Level 0: scan global 16-bit histogram, find boundary bin ----
    {
        const uint4* gh = reinterpret_cast<const uint4*>(g_hist + e * 65536);
        unsigned lsum = 0;
#pragma unroll
        for (int q = 0; q < 16; ++q) {
            uint4 u = gh[tid * 16 + q];
            lsum += u.x + u.y + u.z + u.w;
        }
        unsigned si = lsum;
#pragma unroll
        for (int o = 1; o < 32; o <<= 1) {
            unsigned n = __shfl_up_sync(0xffffffffu, si, o);
            if (lane >= (unsigned)o) si += n;
        }
        if (lane == 31) s_wsum[wid] = si;
        __syncthreads();
        if (wid == 0) {
            unsigned w = s_wsum[lane];
            unsigned wi = w;
#pragma unroll
            for (int o = 1; o < 32; o <<= 1) {
                unsigned n = __shfl_up_sync(0xffffffffu, wi, o);
                if (lane >= (unsigned)o) wi += n;
            }
            s_wsum[lane] = wi - w;
        }
        __syncthreads();
        unsigned base = s_wsum[wid] + (si - lsum);   // exclusive prefix over threads
        if ((int)base < KSEL && (int)(base + lsum) >= KSEL) {
            const unsigned* gb = g_hist + e * 65536 + tid * 64;
            unsigned run = base;
            for (int j = 0; j < 64; ++j) {
                unsigned c = gb[j];
                if ((int)run < KSEL && (int)(run + c) >= KSEL) {
                    s_bin = tid * 64 + j;
                    s_before = run;
                    if ((int)(run + c) == KSEL) s_exact = 1;
                    break;
                }
                run += c;
            }
        }
        __syncthreads();
        if (tid == 0) {
            s_want = KSEL - (int)s_before;
            s_pref = (unsigned long long)(unsigned)s_bin << 30;
            s_mask = 0xFFFFull << 30;
        }
        __syncthreads();
    }

    unsigned long long Kstar;
    if (s_exact) {
        Kstar = s_pref | (~s_mask & MASK46);
    } else {
        // ---- In-block levels over register keys ----
        const int shifts[3] = {18, 6, 0};
        const int nbits [3] = {12, 12, 6};
        for (int lvl = 0; lvl < 3; ++lvl) {
            const int shift = shifts[lvl];
            const int nb    = 1 << nbits[lvl];
            const int wantLoc              = s_want;
            const unsigned long long mask  = s_mask;
            const unsigned long long pref  = s_pref;

            for (int i = tid; i < HC * 4096; i += K2_THREADS) hist[i] = 0u;
            __syncthreads();

            unsigned int* myhist = hist + (wid & (HC - 1)) * 4096;
#pragma unroll
            for (int r = 0; r < 16; ++r) {
                unsigned long long K = ((unsigned long long)kreg[r] << 14)
                                     | (unsigned)(tid + r * K2_THREADS);
                bool m = ((K & mask) == pref);
                unsigned active = __ballot_sync(0xffffffffu, m);
                if (m) {
                    int bin = (int)((K >> shift) & (unsigned)(nb - 1));
                    unsigned same = __match_any_sync(active, bin);
                    if ((int)lane == (__ffs(same) - 1))
                        atomicAdd(&myhist[bin], (unsigned)__popc(same));
                }
            }
            __syncthreads();

            // Sum copies + hierarchical inclusive scan over 4096 bins (4/thread).
            {
                unsigned v[4];
                unsigned sthr = 0;
#pragma unroll
                for (int j = 0; j < 4; ++j) {
                    int b = 4 * tid + j;
                    unsigned t = 0;
#pragma unroll
                    for (int c = 0; c < HC; ++c) t += hist[c * 4096 + b];
                    v[j] = t; sthr += t;
                }
                unsigned si = sthr;
#pragma unroll
                for (int o = 1; o < 32; o <<= 1) {
                    unsigned n = __shfl_up_sync(0xffffffffu, si, o);
                    if (lane >= (unsigned)o) si += n;
                }
                if (lane == 31) s_wsum[wid] = si;
                __syncthreads();
                if (wid == 0) {
                    unsigned w = s_wsum[lane];
                    unsigned wi = w;
#pragma unroll
                    for (int o = 1; o < 32; o <<= 1) {
                        unsigned n = __shfl_up_sync(0xffffffffu, wi, o);
                        if (lane >= (unsigned)o) wi += n;
                    }
                    s_wsum[lane] = wi - w;
                }
                __syncthreads();
                unsigned run = s_wsum[wid] + (si - sthr);
#pragma unroll
                for (int j = 0; j < 4; ++j) {
                    run += v[j];
                    hscan[4 * tid + j] = run;
                }
            }
            __syncthreads();

            for (int i = tid; i < nb; i += K2_THREADS) {
                unsigned c = hscan[i];
                unsigned p = (i > 0) ? hscan[i - 1] : 0u;
                if ((int)c >= wantLoc && (int)p < wantLoc) {
                    s_bin = i; s_before = p;
                    if ((int)c == wantLoc) s_exact = 1;
                }
            }
            __syncthreads();
            if (tid == 0) {
                s_want = wantLoc - (int)s_before;
                s_pref = pref | ((unsigned long long)(unsigned)s_bin << shift);
                s_mask = mask | ((unsigned long long)(unsigned)(nb - 1) << shift);
            }
            __syncthreads();
            if (s_exact) break;
        }
        Kstar = s_pref | (~s_mask & MASK46);   // level 3 exit is always exact
    }

    // Collect exactly 2048 keys <= Kstar (keys unique: index in low bits).
#pragma unroll
    for (int r = 0; r < 16; ++r) {
        unsigned long long K = ((unsigned long long)kreg[r] << 14)
                             | (unsigned)(tid + r * K2_THREADS);
        bool take = (K <= Kstar);
        unsigned bal = __ballot_sync(0xffffffffu, take);
        int base = 0;
        if (lane == 0 && bal) base = atomicAdd(&s_n, __popc(bal));
        base = __shfl_sync(0xffffffffu, base, 0);
        if (take) {
            int pos = base + __popc(bal & ((1u << lane) - 1u));
            sel[pos] = K;
        }
    }
    __syncthreads();

    // ---- Hybrid bitonic sort ascending over sel[2048] ----
    const int g0 = (wid << 6) | (int)lane;
    const int g1 = g0 + 32;
    unsigned long long a = sel[g0];
    unsigned long long b = sel[g1];

    for (int k = 2; k <= KSEL; k <<= 1) {
        int j = k >> 1;
        if (j >= 64) {
            sel[g0] = a; sel[g1] = b;
            __syncthreads();
            for (; j >= 64; j >>= 1) {
                int i = ((tid & ~(j - 1)) << 1) | (tid & (j - 1));
                int l = i | j;
                unsigned long long u = sel[i];
                unsigned long long v = sel[l];
                bool asc = ((i & k) == 0);
                if ((u > v) == asc) { sel[i] = v; sel[l] = u; }
                __syncthreads();
            }
            a = sel[g0]; b = sel[g1];   // j == 32 now
        }
        for (; j >= 1; j >>= 1) {
            if (j == 32) {
                bool asc = ((g0 & k) == 0);
                if ((a > b) == asc) { unsigned long long t = a; a = b; b = t; }
            } else {
                unsigned long long pa = __shfl_xor_sync(0xffffffffu, a, j);
                unsigned long long pb = __shfl_xor_sync(0xffffffffu, b, j);
                bool lower = ((lane & (unsigned)j) == 0u);
                bool ascA  = ((g0 & k) == 0);
                bool ascB  = ((g1 & k) == 0);
                unsigned long long amin = (a < pa) ? a : pa;
                unsigned long long amax = (a < pa) ? pa : a;
                unsigned long long bmin = (b < pb) ? b : pb;
                unsigned long long bmax = (b < pb) ? pb : b;
                a = (lower == ascA) ? amin : amax;
                b = (lower == ascB) ? bmin : bmax;
            }
        }
    }

    // Emit from registers.
    {
        float scA = __uint_as_float(~(unsigned)(a >> 14));
        float scB = __uint_as_float(~(unsigned)(b >> 14));
        out[e * KSEL + g0] = scA;
        out[e * KSEL + g1] = scB;
        if (writeIdx) {
            out[NE * KSEL + e * KSEL + g0] = (float)(unsigned)(a & 0x3FFFu);
            out[NE * KSEL + e * KSEL + g1] = (float)(unsigned)(b & 0x3FFFu);
        }
    }
}

// ---------------------------------------------------------------------------
extern "C" void kernel_launch(void* const* d_in, const int* in_sizes, int n_in,
                              void* d_out, int out_size)
{
    const float* x = (const float*)d_in[0];   // [16384, 2048] f32
    const float* W = (const float*)d_in[1];   // [8, 2048] f32
    float* out = (float*)d_out;

    const int SMEM2 = 65536 + 16384 + 16384;  // 98304

    cudaFuncSetAttribute(k2_topk, cudaFuncAttributeMaxDynamicSharedMemorySize, SMEM2);

    void* hp = nullptr;
    cudaGetSymbolAddress(&hp, g_hist);
    cudaMemsetAsync(hp, 0, sizeof(unsigned) * NE * 65536);

    const int writeIdx = (out_size >= 2 * NE * KSEL) ? 1 : 0;

    k1_gemv<<<T_TOKENS / TILE_T, K1_THREADS>>>(x, W);
    k2_topk<<<NE, K2_THREADS, SMEM2>>>(out, writeIdx);
}